// round 4
// baseline (speedup 1.0000x reference)
#include <cuda_runtime.h>

#define LCOLS 4096
#define NSTAGES 12
#define TPB 512
#define NBATCH 8192

// Swizzle: XOR bit4 with j's bit11, bit2 with j's bit5. Only touches bits >=2;
// bits 5/11 constant within a 4-aligned group -> float4 halves stay contiguous.
__device__ __forceinline__ int swz(int j) {
    return j ^ (((j >> 11) & 1) << 4) ^ (((j >> 5) & 1) << 2);
}

// y[j] <- W[s][j][0]*y[j] + W[s][j][1]*y[j ^ (1<<s)]
// Phase 1: thread owns 8 contiguous cols (bits 0-2 in-thread, bits 3-7 lane -> shfl)
//          -> stages 0..7. One swizzled smem store.
// Phase 2: thread gathers j = b11*2048 + k*256 + low8 (k = bits 8-10 in-thread,
//          b11 = lane bit 4 -> shfl mask 16) -> stages 8..11. Direct global store.
template <int R>
__global__ __launch_bounds__(TPB, 1)
void butterfly_kernel(const float* __restrict__ x,
                      const float* __restrict__ W,
                      float* __restrict__ out,
                      int rowbase)
{
    extern __shared__ float sm[];   // R * LCOLS floats
    const int tid  = threadIdx.x;
    const int row0 = rowbase + blockIdx.x * R;
    const int j0   = tid * 8;

    float y[R][8];

    // ---- load R rows x 8 cols, vectorized & coalesced ----
    #pragma unroll
    for (int r = 0; r < R; ++r) {
        const float4* p = reinterpret_cast<const float4*>(
            x + (size_t)(row0 + r) * LCOLS + j0);
        float4 a = __ldg(p);
        float4 b = __ldg(p + 1);
        y[r][0]=a.x; y[r][1]=a.y; y[r][2]=a.z; y[r][3]=a.w;
        y[r][4]=b.x; y[r][5]=b.y; y[r][6]=b.z; y[r][7]=b.w;
    }

    // ---- phase 1: stages 0..7 (regs + shfl) ----
    #pragma unroll
    for (int s = 0; s < 8; ++s) {
        float w0[8], w1[8];
        const float4* wp = reinterpret_cast<const float4*>(
            W + (size_t)s * (LCOLS * 2) + j0 * 2);
        float4 wA = __ldg(wp + 0), wB = __ldg(wp + 1);
        float4 wC = __ldg(wp + 2), wD = __ldg(wp + 3);
        w0[0]=wA.x; w1[0]=wA.y; w0[1]=wA.z; w1[1]=wA.w;
        w0[2]=wB.x; w1[2]=wB.y; w0[3]=wB.z; w1[3]=wB.w;
        w0[4]=wC.x; w1[4]=wC.y; w0[5]=wC.z; w1[5]=wC.w;
        w0[6]=wD.x; w1[6]=wD.y; w0[7]=wD.z; w1[7]=wD.w;

        if (s < 3) {
            const int d = 1 << s;                     // 1,2,4 in-thread
            #pragma unroll
            for (int r = 0; r < R; ++r) {
                float nt[8];
                #pragma unroll
                for (int c = 0; c < 8; ++c)
                    nt[c] = fmaf(w0[c], y[r][c], w1[c] * y[r][c ^ d]);
                #pragma unroll
                for (int c = 0; c < 8; ++c) y[r][c] = nt[c];
            }
        } else {
            const int m = 1 << (s - 3);               // lane xor 1..16
            #pragma unroll
            for (int r = 0; r < R; ++r) {
                #pragma unroll
                for (int c = 0; c < 8; ++c) {
                    float p = __shfl_xor_sync(0xffffffffu, y[r][c], m);
                    y[r][c] = fmaf(w0[c], y[r][c], w1[c] * p);
                }
            }
        }
    }

    // ---- single swizzled smem store: element j lands at sm[swz(j)] ----
    {
        const int s0 = swz(j0);        // elements j0..j0+3
        const int s1 = swz(j0 + 4);    // elements j0+4..j0+7
        #pragma unroll
        for (int r = 0; r < R; ++r) {
            *reinterpret_cast<float4*>(&sm[r * LCOLS + s0]) =
                make_float4(y[r][0], y[r][1], y[r][2], y[r][3]);
            *reinterpret_cast<float4*>(&sm[r * LCOLS + s1]) =
                make_float4(y[r][4], y[r][5], y[r][6], y[r][7]);
        }
    }
    __syncthreads();

    // ---- phase 2: stages 8..11 ----
    const int l     = tid & 31;
    const int w     = tid >> 5;
    const int b11   = l >> 4;                // stage-11 partner = lane ^ 16
    const int low8  = (w << 4) | (l & 15);   // bits 0..7 of j
    const int jbase = b11 * 2048 + low8;     // j(k) = jbase + k*256
    const int sjbase = swz(jbase);           // bits 5,11 of j constant per thread

    // weights for stages 8..11, 8 columns each, loaded once, reused for all rows
    float w0p[4][8], w1p[4][8];
    #pragma unroll
    for (int s4 = 0; s4 < 4; ++s4) {
        #pragma unroll
        for (int k = 0; k < 8; ++k) {
            const float2 ww = __ldg(reinterpret_cast<const float2*>(
                W + (size_t)(8 + s4) * (LCOLS * 2) + 2 * (jbase + k * 256)));
            w0p[s4][k] = ww.x;
            w1p[s4][k] = ww.y;
        }
    }

    #pragma unroll
    for (int r = 0; r < R; ++r) {
        float v[8];
        #pragma unroll
        for (int k = 0; k < 8; ++k)
            v[k] = sm[r * LCOLS + sjbase + k * 256];   // conflict-free gather

        // stages 8,9,10 : butterflies on k bits 0,1,2
        #pragma unroll
        for (int sb = 0; sb < 3; ++sb) {
            const int d = 1 << sb;
            float nv[8];
            #pragma unroll
            for (int k = 0; k < 8; ++k)
                nv[k] = fmaf(w0p[sb][k], v[k], w1p[sb][k] * v[k ^ d]);
            #pragma unroll
            for (int k = 0; k < 8; ++k) v[k] = nv[k];
        }

        // stage 11 : partner is lane^16 (b11 flip)
        #pragma unroll
        for (int k = 0; k < 8; ++k) {
            float p = __shfl_xor_sync(0xffffffffu, v[k], 16);
            v[k] = fmaf(w0p[3][k], v[k], w1p[3][k] * p);
        }

        // direct global store: per k, lanes 0-15 and 16-31 each cover 64B runs
        float* op = out + (size_t)(row0 + r) * LCOLS + jbase;
        #pragma unroll
        for (int k = 0; k < 8; ++k)
            op[k * 256] = v[k];
    }
}

extern "C" void kernel_launch(void* const* d_in, const int* in_sizes, int n_in,
                              void* d_out, int out_size) {
    const float* x;
    const float* W;
    if (in_sizes[0] == NSTAGES * LCOLS * 2) {   // W has 98304 elements
        W = (const float*)d_in[0];
        x = (const float*)d_in[1];
    } else {
        x = (const float*)d_in[0];
        W = (const float*)d_in[1];
    }
    float* out = (float*)d_out;

    const int smem12 = 12 * LCOLS * sizeof(float);  // 192 KB
    const int smem8  =  8 * LCOLS * sizeof(float);  // 128 KB
    cudaFuncSetAttribute(butterfly_kernel<12>,
                         cudaFuncAttributeMaxDynamicSharedMemorySize, smem12);
    cudaFuncSetAttribute(butterfly_kernel<8>,
                         cudaFuncAttributeMaxDynamicSharedMemorySize, smem8);

    // 8192 = 682*12 + 8
    butterfly_kernel<12><<<682, TPB, smem12>>>(x, W, out, 0);
    butterfly_kernel<8><<<1, TPB, smem8>>>(x, W, out, 682 * 12);
}